// round 7
// baseline (speedup 1.0000x reference)
#include <cuda_runtime.h>
#include <math.h>

// ---------------- problem constants ----------------
#define EMBED    1024
#define HEADS    16
#define HEAD_DIM 64
#define FFDIM    4096
#define LAYERS   4
#define BATCH    2
#define SEQ      2048
#define ROWS     (BATCH * SEQ)   // 4096
#define BANDW    46              // ceil(sqrt(2048))

// attention tiling
#define QT    64
#define KT    (QT + 2 * BANDW)   // 156
#define PITCH 68                 // padded row pitch (floats) for Q/K/V smem

// ---------------- scratch (device globals; no allocation allowed) ----------------
__device__ float g_q[ROWS * EMBED];
__device__ float g_k[ROWS * EMBED];
__device__ float g_v[ROWS * EMBED];
__device__ float g_attn[ROWS * EMBED];
__device__ float g_proj[ROWS * EMBED];
__device__ float g_x[ROWS * EMBED];
__device__ float g_x2[ROWS * EMBED];
__device__ float g_ffbuf[ROWS * FFDIM];

// ---------------- SGEMM: C[M,N] = A[M,K] @ W[N,K]^T + bias, optional ReLU ----------------
// 128x128 tile, BK=8, 256 threads, 8x8 per thread, fp32.
__global__ __launch_bounds__(256) void sgemm_nt(
    const float* __restrict__ A, const float* __restrict__ W,
    const float* __restrict__ bias, float* __restrict__ C,
    int M, int N, int K, int relu)
{
    __shared__ float As[8][128];
    __shared__ float Bs[8][128];
    const int tid = threadIdx.x;
    const int m0 = blockIdx.y * 128;
    const int n0 = blockIdx.x * 128;
    const int lrow = tid >> 1;
    const int lcol = (tid & 1) * 4;
    const float* Ap = A + (size_t)(m0 + lrow) * K + lcol;
    const float* Wp = W + (size_t)(n0 + lrow) * K + lcol;
    const int tx = tid & 15;
    const int ty = tid >> 4;

    float acc[8][8];
#pragma unroll
    for (int i = 0; i < 8; i++)
#pragma unroll
        for (int j = 0; j < 8; j++) acc[i][j] = 0.f;

    float4 a = *(const float4*)(Ap);
    float4 b = *(const float4*)(Wp);
    for (int k0 = 0; k0 < K; k0 += 8) {
        As[lcol + 0][lrow] = a.x;
        As[lcol + 1][lrow] = a.y;
        As[lcol + 2][lrow] = a.z;
        As[lcol + 3][lrow] = a.w;
        Bs[lcol + 0][lrow] = b.x;
        Bs[lcol + 1][lrow] = b.y;
        Bs[lcol + 2][lrow] = b.z;
        Bs[lcol + 3][lrow] = b.w;
        __syncthreads();
        if (k0 + 8 < K) {
            a = *(const float4*)(Ap + k0 + 8);
            b = *(const float4*)(Wp + k0 + 8);
        }
#pragma unroll
        for (int kk = 0; kk < 8; kk++) {
            float ar[8], br[8];
            *(float4*)(ar)     = *(const float4*)(&As[kk][ty * 4]);
            *(float4*)(ar + 4) = *(const float4*)(&As[kk][64 + ty * 4]);
            *(float4*)(br)     = *(const float4*)(&Bs[kk][tx * 4]);
            *(float4*)(br + 4) = *(const float4*)(&Bs[kk][64 + tx * 4]);
#pragma unroll
            for (int i = 0; i < 8; i++)
#pragma unroll
                for (int j = 0; j < 8; j++)
                    acc[i][j] += ar[i] * br[j];
        }
        __syncthreads();
    }

    float4 bias0 = *(const float4*)(bias + n0 + tx * 4);
    float4 bias1 = *(const float4*)(bias + n0 + 64 + tx * 4);
#pragma unroll
    for (int i = 0; i < 8; i++) {
        int row = m0 + ((i < 4) ? (ty * 4 + i) : (64 + ty * 4 + (i - 4)));
        float4 r0, r1;
        r0.x = acc[i][0] + bias0.x;
        r0.y = acc[i][1] + bias0.y;
        r0.z = acc[i][2] + bias0.z;
        r0.w = acc[i][3] + bias0.w;
        r1.x = acc[i][4] + bias1.x;
        r1.y = acc[i][5] + bias1.y;
        r1.z = acc[i][6] + bias1.z;
        r1.w = acc[i][7] + bias1.w;
        if (relu) {
            r0.x = fmaxf(r0.x, 0.f); r0.y = fmaxf(r0.y, 0.f);
            r0.z = fmaxf(r0.z, 0.f); r0.w = fmaxf(r0.w, 0.f);
            r1.x = fmaxf(r1.x, 0.f); r1.y = fmaxf(r1.y, 0.f);
            r1.z = fmaxf(r1.z, 0.f); r1.w = fmaxf(r1.w, 0.f);
        }
        *(float4*)(C + (size_t)row * N + n0 + tx * 4)      = r0;
        *(float4*)(C + (size_t)row * N + n0 + 64 + tx * 4) = r1;
    }
}

// ---------------- banded attention ----------------
// One CTA per (batch, head, 64-query tile). Keys/values windowed to 156 rows.
// Layout of q/k/v/o buffers: [B, S, H*D] with head h occupying cols h*64..h*64+63.
#define ATTN_SMEM_FLOATS (QT * PITCH + 2 * KT * PITCH + QT * KT)
#define ATTN_SMEM_BYTES  (ATTN_SMEM_FLOATS * 4)

__global__ __launch_bounds__(256) void band_attn(
    const float* __restrict__ q, const float* __restrict__ k,
    const float* __restrict__ v, float* __restrict__ o)
{
    extern __shared__ float sm[];
    float* Qs = sm;                       // QT * PITCH
    float* Ks = Qs + QT * PITCH;          // KT * PITCH
    float* Vs = Ks + KT * PITCH;          // KT * PITCH
    float* Ss = Vs + KT * PITCH;          // QT * KT

    const int t  = threadIdx.x;           // 256
    const int q0 = blockIdx.x * QT;
    const int h  = blockIdx.y;
    const int b  = blockIdx.z;
    const size_t hoff = (size_t)h * HEAD_DIM;

    // load Q tile
    for (int idx = t; idx < QT * 16; idx += 256) {
        int i  = idx >> 4;
        int d4 = (idx & 15) * 4;
        float4 val = *(const float4*)(q + ((size_t)(b * SEQ + q0 + i) * EMBED) + hoff + d4);
        Qs[i * PITCH + d4 + 0] = val.x;
        Qs[i * PITCH + d4 + 1] = val.y;
        Qs[i * PITCH + d4 + 2] = val.z;
        Qs[i * PITCH + d4 + 3] = val.w;
    }
    // load K/V window (zero-fill outside sequence)
    for (int idx = t; idx < KT * 16; idx += 256) {
        int jj = idx >> 4;
        int d4 = (idx & 15) * 4;
        int j  = q0 - BANDW + jj;
        float4 kv = make_float4(0.f, 0.f, 0.f, 0.f);
        float4 vv = make_float4(0.f, 0.f, 0.f, 0.f);
        if (j >= 0 && j < SEQ) {
            size_t base = ((size_t)(b * SEQ + j) * EMBED) + hoff + d4;
            kv = *(const float4*)(k + base);
            vv = *(const float4*)(v + base);
        }
        Ks[jj * PITCH + d4 + 0] = kv.x;
        Ks[jj * PITCH + d4 + 1] = kv.y;
        Ks[jj * PITCH + d4 + 2] = kv.z;
        Ks[jj * PITCH + d4 + 3] = kv.w;
        Vs[jj * PITCH + d4 + 0] = vv.x;
        Vs[jj * PITCH + d4 + 1] = vv.y;
        Vs[jj * PITCH + d4 + 2] = vv.z;
        Vs[jj * PITCH + d4 + 3] = vv.w;
    }
    __syncthreads();

    // scores
    const float scale = 0.125f;  // 1/sqrt(64)
    const int i  = t >> 2;
    const int jl = t & 3;
    for (int jj = jl; jj < KT; jj += 4) {
        int j = q0 - BANDW + jj;
        float sres = -1e9f;
        if (jj >= i && jj <= i + 2 * BANDW && j >= 0 && j < SEQ) {
            const float4* qp = (const float4*)(Qs + i * PITCH);
            const float4* kp = (const float4*)(Ks + jj * PITCH);
            float accv = 0.f;
#pragma unroll
            for (int d4 = 0; d4 < 16; d4++) {
                float4 aa = qp[d4], cc = kp[d4];
                accv += aa.x * cc.x + aa.y * cc.y + aa.z * cc.z + aa.w * cc.w;
            }
            sres = accv * scale;
        }
        Ss[i * KT + jj] = sres;
    }
    __syncthreads();

    // softmax (one thread per query row)
    if (t < QT) {
        float* srow = Ss + t * KT;
        float mx = -1e30f;
        for (int jj = 0; jj < KT; jj++) mx = fmaxf(mx, srow[jj]);
        float sum = 0.f;
        for (int jj = 0; jj < KT; jj++) {
            float e = expf(srow[jj] - mx);
            srow[jj] = e;
            sum += e;
        }
        float inv = 1.f / sum;
        for (int jj = 0; jj < KT; jj++) srow[jj] *= inv;
    }
    __syncthreads();

    // output: thread handles (i, 16 contiguous dims)
    const int dblk = (t & 3) * 16;
    float acc[16];
#pragma unroll
    for (int kk = 0; kk < 16; kk++) acc[kk] = 0.f;
    for (int jj = 0; jj < KT; jj++) {
        float p = Ss[i * KT + jj];
        const float4* vp = (const float4*)(Vs + jj * PITCH + dblk);
#pragma unroll
        for (int k4 = 0; k4 < 4; k4++) {
            float4 vv = vp[k4];
            acc[k4 * 4 + 0] += p * vv.x;
            acc[k4 * 4 + 1] += p * vv.y;
            acc[k4 * 4 + 2] += p * vv.z;
            acc[k4 * 4 + 3] += p * vv.w;
        }
    }
    float* op = o + ((size_t)(b * SEQ + q0 + i) * EMBED) + hoff + dblk;
#pragma unroll
    for (int k4 = 0; k4 < 4; k4++) {
        float4 r;
        r.x = acc[k4 * 4 + 0];
        r.y = acc[k4 * 4 + 1];
        r.z = acc[k4 * 4 + 2];
        r.w = acc[k4 * 4 + 3];
        *(float4*)(op + k4 * 4) = r;
    }
}

// ---------------- fused residual add + LayerNorm ----------------
// y = LN(r + p) * g + be ; one block per row of 1024, 256 threads, float4 each.
__global__ __launch_bounds__(256) void add_ln(
    const float* __restrict__ r, const float* __restrict__ p,
    const float* __restrict__ g, const float* __restrict__ be,
    float* __restrict__ y)
{
    const int row = blockIdx.x;
    const int t = threadIdx.x;
    const size_t base = (size_t)row * EMBED + t * 4;
    float4 rv = *(const float4*)(r + base);
    float4 pv = *(const float4*)(p + base);
    float z0 = rv.x + pv.x, z1 = rv.y + pv.y, z2 = rv.z + pv.z, z3 = rv.w + pv.w;
    float s  = z0 + z1 + z2 + z3;
    float sq = z0 * z0 + z1 * z1 + z2 * z2 + z3 * z3;
#pragma unroll
    for (int off = 16; off > 0; off >>= 1) {
        s  += __shfl_xor_sync(0xffffffffu, s, off);
        sq += __shfl_xor_sync(0xffffffffu, sq, off);
    }
    __shared__ float ws[8], wsq[8];
    __shared__ float mu_s, rstd_s;
    const int warp = t >> 5, lane = t & 31;
    if (lane == 0) { ws[warp] = s; wsq[warp] = sq; }
    __syncthreads();
    if (t == 0) {
        float ts = 0.f, tsq = 0.f;
#pragma unroll
        for (int wdx = 0; wdx < 8; wdx++) { ts += ws[wdx]; tsq += wsq[wdx]; }
        float mu = ts * (1.f / EMBED);
        float var = tsq * (1.f / EMBED) - mu * mu;
        mu_s = mu;
        rstd_s = rsqrtf(var + 1e-5f);
    }
    __syncthreads();
    float mu = mu_s, rstd = rstd_s;
    float4 gv = *(const float4*)(g + t * 4);
    float4 bv = *(const float4*)(be + t * 4);
    float4 out;
    out.x = (z0 - mu) * rstd * gv.x + bv.x;
    out.y = (z1 - mu) * rstd * gv.y + bv.y;
    out.z = (z2 - mu) * rstd * gv.z + bv.z;
    out.w = (z3 - mu) * rstd * gv.w + bv.w;
    *(float4*)(y + base) = out;
}

// ---------------- launch ----------------
extern "C" void kernel_launch(void* const* d_in, const int* in_sizes, int n_in,
                              void* d_out, int out_size)
{
    static bool inited = false;
    static float *pq, *pk, *pv, *pattn, *pproj, *px, *px2, *pff;
    if (!inited) {
        cudaGetSymbolAddress((void**)&pq,    g_q);
        cudaGetSymbolAddress((void**)&pk,    g_k);
        cudaGetSymbolAddress((void**)&pv,    g_v);
        cudaGetSymbolAddress((void**)&pattn, g_attn);
        cudaGetSymbolAddress((void**)&pproj, g_proj);
        cudaGetSymbolAddress((void**)&px,    g_x);
        cudaGetSymbolAddress((void**)&px2,   g_x2);
        cudaGetSymbolAddress((void**)&pff,   g_ffbuf);
        cudaFuncSetAttribute(band_attn, cudaFuncAttributeMaxDynamicSharedMemorySize,
                             ATTN_SMEM_BYTES);
        inited = true;
    }

    const float* x   = (const float*)d_in[0];
    const float* Wq  = (const float*)d_in[1];
    const float* bq  = (const float*)d_in[2];
    const float* Wk  = (const float*)d_in[3];
    const float* bk  = (const float*)d_in[4];
    const float* Wv  = (const float*)d_in[5];
    const float* bv  = (const float*)d_in[6];
    const float* Wo  = (const float*)d_in[7];
    const float* bo  = (const float*)d_in[8];
    const float* W1  = (const float*)d_in[9];
    const float* b1  = (const float*)d_in[10];
    const float* W2  = (const float*)d_in[11];
    const float* b2  = (const float*)d_in[12];
    const float* g1  = (const float*)d_in[13];
    const float* be1 = (const float*)d_in[14];
    const float* g2  = (const float*)d_in[15];
    const float* be2 = (const float*)d_in[16];
    float* out = (float*)d_out;

    const dim3 gE(EMBED / 128, ROWS / 128);   // (8, 32)
    const dim3 gF(FFDIM / 128, ROWS / 128);   // (32, 32)
    const dim3 gA(SEQ / QT, HEADS, BATCH);    // (32, 16, 2)

    const float* cur = x;
    for (int L = 0; L < LAYERS; L++) {
        const size_t oEE = (size_t)L * EMBED * EMBED;
        const size_t oE  = (size_t)L * EMBED;
        const size_t oFE = (size_t)L * FFDIM * EMBED;
        const size_t oF  = (size_t)L * FFDIM;

        sgemm_nt<<<gE, 256>>>(cur, Wq + oEE, bq + oE, pq, ROWS, EMBED, EMBED, 0);
        sgemm_nt<<<gE, 256>>>(cur, Wk + oEE, bk + oE, pk, ROWS, EMBED, EMBED, 0);
        sgemm_nt<<<gE, 256>>>(cur, Wv + oEE, bv + oE, pv, ROWS, EMBED, EMBED, 0);

        band_attn<<<gA, 256, ATTN_SMEM_BYTES>>>(pq, pk, pv, pattn);

        sgemm_nt<<<gE, 256>>>(pattn, Wo + oEE, bo + oE, pproj, ROWS, EMBED, EMBED, 0);
        add_ln<<<ROWS, 256>>>(cur, pproj, g1 + oE, be1 + oE, px2);

        sgemm_nt<<<gF, 256>>>(px2, W1 + oFE, b1 + oF, pff, ROWS, FFDIM, EMBED, 1);
        sgemm_nt<<<gE, 256>>>(pff, W2 + oFE, b2 + oE, pproj, ROWS, EMBED, FFDIM, 0);

        float* dst = (L == LAYERS - 1) ? out : px;
        add_ln<<<ROWS, 256>>>(px2, pproj, g2 + oE, be2 + oE, dst);
        cur = px;
    }
}

// round 8
// speedup vs baseline: 1.0018x; 1.0018x over previous
#include <cuda_runtime.h>
#include <math.h>

// ---------------- problem constants ----------------
#define EMBED    1024
#define HEADS    16
#define HEAD_DIM 64
#define FFDIM    4096
#define LAYERS   4
#define BATCH    2
#define SEQ      2048
#define ROWS     (BATCH * SEQ)   // 4096
#define BANDW    46              // ceil(sqrt(2048))

// attention tiling
#define QT    64
#define KT    (QT + 2 * BANDW)   // 156
#define PITCH 68                 // padded row pitch (floats) for Q/K/V smem

// ---------------- scratch (device globals; no allocation allowed) ----------------
__device__ float g_q[ROWS * EMBED];
__device__ float g_k[ROWS * EMBED];
__device__ float g_v[ROWS * EMBED];
__device__ float g_attn[ROWS * EMBED];
__device__ float g_proj[ROWS * EMBED];
__device__ float g_x[ROWS * EMBED];
__device__ float g_x2[ROWS * EMBED];
__device__ float g_ffbuf[ROWS * FFDIM];

// ---------------- SGEMM: C[M,N] = A[M,K] @ W[N,K]^T + bias, optional ReLU ----------------
// 128x128 tile, BK=8, 256 threads, 8x8 per thread, fp32.
__global__ __launch_bounds__(256) void sgemm_nt(
    const float* __restrict__ A, const float* __restrict__ W,
    const float* __restrict__ bias, float* __restrict__ C,
    int M, int N, int K, int relu)
{
    __shared__ float As[8][128];
    __shared__ float Bs[8][128];
    const int tid = threadIdx.x;
    const int m0 = blockIdx.y * 128;
    const int n0 = blockIdx.x * 128;
    const int lrow = tid >> 1;
    const int lcol = (tid & 1) * 4;
    const float* Ap = A + (size_t)(m0 + lrow) * K + lcol;
    const float* Wp = W + (size_t)(n0 + lrow) * K + lcol;
    const int tx = tid & 15;
    const int ty = tid >> 4;

    float acc[8][8];
#pragma unroll
    for (int i = 0; i < 8; i++)
#pragma unroll
        for (int j = 0; j < 8; j++) acc[i][j] = 0.f;

    float4 a = *(const float4*)(Ap);
    float4 b = *(const float4*)(Wp);
    for (int k0 = 0; k0 < K; k0 += 8) {
        As[lcol + 0][lrow] = a.x;
        As[lcol + 1][lrow] = a.y;
        As[lcol + 2][lrow] = a.z;
        As[lcol + 3][lrow] = a.w;
        Bs[lcol + 0][lrow] = b.x;
        Bs[lcol + 1][lrow] = b.y;
        Bs[lcol + 2][lrow] = b.z;
        Bs[lcol + 3][lrow] = b.w;
        __syncthreads();
        if (k0 + 8 < K) {
            a = *(const float4*)(Ap + k0 + 8);
            b = *(const float4*)(Wp + k0 + 8);
        }
#pragma unroll
        for (int kk = 0; kk < 8; kk++) {
            float ar[8], br[8];
            *(float4*)(ar)     = *(const float4*)(&As[kk][ty * 4]);
            *(float4*)(ar + 4) = *(const float4*)(&As[kk][64 + ty * 4]);
            *(float4*)(br)     = *(const float4*)(&Bs[kk][tx * 4]);
            *(float4*)(br + 4) = *(const float4*)(&Bs[kk][64 + tx * 4]);
#pragma unroll
            for (int i = 0; i < 8; i++)
#pragma unroll
                for (int j = 0; j < 8; j++)
                    acc[i][j] += ar[i] * br[j];
        }
        __syncthreads();
    }

    float4 bias0 = *(const float4*)(bias + n0 + tx * 4);
    float4 bias1 = *(const float4*)(bias + n0 + 64 + tx * 4);
#pragma unroll
    for (int i = 0; i < 8; i++) {
        int row = m0 + ((i < 4) ? (ty * 4 + i) : (64 + ty * 4 + (i - 4)));
        float4 r0, r1;
        r0.x = acc[i][0] + bias0.x;
        r0.y = acc[i][1] + bias0.y;
        r0.z = acc[i][2] + bias0.z;
        r0.w = acc[i][3] + bias0.w;
        r1.x = acc[i][4] + bias1.x;
        r1.y = acc[i][5] + bias1.y;
        r1.z = acc[i][6] + bias1.z;
        r1.w = acc[i][7] + bias1.w;
        if (relu) {
            r0.x = fmaxf(r0.x, 0.f); r0.y = fmaxf(r0.y, 0.f);
            r0.z = fmaxf(r0.z, 0.f); r0.w = fmaxf(r0.w, 0.f);
            r1.x = fmaxf(r1.x, 0.f); r1.y = fmaxf(r1.y, 0.f);
            r1.z = fmaxf(r1.z, 0.f); r1.w = fmaxf(r1.w, 0.f);
        }
        *(float4*)(C + (size_t)row * N + n0 + tx * 4)      = r0;
        *(float4*)(C + (size_t)row * N + n0 + 64 + tx * 4) = r1;
    }
}

// ---------------- banded attention ----------------
// One CTA per (batch, head, 64-query tile). Keys/values windowed to 156 rows.
// Layout of q/k/v/o buffers: [B, S, H*D] with head h occupying cols h*64..h*64+63.
#define ATTN_SMEM_FLOATS (QT * PITCH + 2 * KT * PITCH + QT * KT)
#define ATTN_SMEM_BYTES  (ATTN_SMEM_FLOATS * 4)

__global__ __launch_bounds__(256) void band_attn(
    const float* __restrict__ q, const float* __restrict__ k,
    const float* __restrict__ v, float* __restrict__ o)
{
    extern __shared__ float sm[];
    float* Qs = sm;                       // QT * PITCH
    float* Ks = Qs + QT * PITCH;          // KT * PITCH
    float* Vs = Ks + KT * PITCH;          // KT * PITCH
    float* Ss = Vs + KT * PITCH;          // QT * KT

    const int t  = threadIdx.x;           // 256
    const int q0 = blockIdx.x * QT;
    const int h  = blockIdx.y;
    const int b  = blockIdx.z;
    const size_t hoff = (size_t)h * HEAD_DIM;

    // load Q tile
    for (int idx = t; idx < QT * 16; idx += 256) {
        int i  = idx >> 4;
        int d4 = (idx & 15) * 4;
        float4 val = *(const float4*)(q + ((size_t)(b * SEQ + q0 + i) * EMBED) + hoff + d4);
        Qs[i * PITCH + d4 + 0] = val.x;
        Qs[i * PITCH + d4 + 1] = val.y;
        Qs[i * PITCH + d4 + 2] = val.z;
        Qs[i * PITCH + d4 + 3] = val.w;
    }
    // load K/V window (zero-fill outside sequence)
    for (int idx = t; idx < KT * 16; idx += 256) {
        int jj = idx >> 4;
        int d4 = (idx & 15) * 4;
        int j  = q0 - BANDW + jj;
        float4 kv = make_float4(0.f, 0.f, 0.f, 0.f);
        float4 vv = make_float4(0.f, 0.f, 0.f, 0.f);
        if (j >= 0 && j < SEQ) {
            size_t base = ((size_t)(b * SEQ + j) * EMBED) + hoff + d4;
            kv = *(const float4*)(k + base);
            vv = *(const float4*)(v + base);
        }
        Ks[jj * PITCH + d4 + 0] = kv.x;
        Ks[jj * PITCH + d4 + 1] = kv.y;
        Ks[jj * PITCH + d4 + 2] = kv.z;
        Ks[jj * PITCH + d4 + 3] = kv.w;
        Vs[jj * PITCH + d4 + 0] = vv.x;
        Vs[jj * PITCH + d4 + 1] = vv.y;
        Vs[jj * PITCH + d4 + 2] = vv.z;
        Vs[jj * PITCH + d4 + 3] = vv.w;
    }
    __syncthreads();

    // scores
    const float scale = 0.125f;  // 1/sqrt(64)
    const int i  = t >> 2;
    const int jl = t & 3;
    for (int jj = jl; jj < KT; jj += 4) {
        int j = q0 - BANDW + jj;
        float sres = -1e9f;
        if (jj >= i && jj <= i + 2 * BANDW && j >= 0 && j < SEQ) {
            const float4* qp = (const float4*)(Qs + i * PITCH);
            const float4* kp = (const float4*)(Ks + jj * PITCH);
            float accv = 0.f;
#pragma unroll
            for (int d4 = 0; d4 < 16; d4++) {
                float4 aa = qp[d4], cc = kp[d4];
                accv += aa.x * cc.x + aa.y * cc.y + aa.z * cc.z + aa.w * cc.w;
            }
            sres = accv * scale;
        }
        Ss[i * KT + jj] = sres;
    }
    __syncthreads();

    // softmax (one thread per query row)
    if (t < QT) {
        float* srow = Ss + t * KT;
        float mx = -1e30f;
        for (int jj = 0; jj < KT; jj++) mx = fmaxf(mx, srow[jj]);
        float sum = 0.f;
        for (int jj = 0; jj < KT; jj++) {
            float e = expf(srow[jj] - mx);
            srow[jj] = e;
            sum += e;
        }
        float inv = 1.f / sum;
        for (int jj = 0; jj < KT; jj++) srow[jj] *= inv;
    }
    __syncthreads();

    // output: thread handles (i, 16 contiguous dims)
    const int dblk = (t & 3) * 16;
    float acc[16];
#pragma unroll
    for (int kk = 0; kk < 16; kk++) acc[kk] = 0.f;
    for (int jj = 0; jj < KT; jj++) {
        float p = Ss[i * KT + jj];
        const float4* vp = (const float4*)(Vs + jj * PITCH + dblk);
#pragma unroll
        for (int k4 = 0; k4 < 4; k4++) {
            float4 vv = vp[k4];
            acc[k4 * 4 + 0] += p * vv.x;
            acc[k4 * 4 + 1] += p * vv.y;
            acc[k4 * 4 + 2] += p * vv.z;
            acc[k4 * 4 + 3] += p * vv.w;
        }
    }
    float* op = o + ((size_t)(b * SEQ + q0 + i) * EMBED) + hoff + dblk;
#pragma unroll
    for (int k4 = 0; k4 < 4; k4++) {
        float4 r;
        r.x = acc[k4 * 4 + 0];
        r.y = acc[k4 * 4 + 1];
        r.z = acc[k4 * 4 + 2];
        r.w = acc[k4 * 4 + 3];
        *(float4*)(op + k4 * 4) = r;
    }
}

// ---------------- fused residual add + LayerNorm ----------------
// y = LN(r + p) * g + be ; one block per row of 1024, 256 threads, float4 each.
__global__ __launch_bounds__(256) void add_ln(
    const float* __restrict__ r, const float* __restrict__ p,
    const float* __restrict__ g, const float* __restrict__ be,
    float* __restrict__ y)
{
    const int row = blockIdx.x;
    const int t = threadIdx.x;
    const size_t base = (size_t)row * EMBED + t * 4;
    float4 rv = *(const float4*)(r + base);
    float4 pv = *(const float4*)(p + base);
    float z0 = rv.x + pv.x, z1 = rv.y + pv.y, z2 = rv.z + pv.z, z3 = rv.w + pv.w;
    float s  = z0 + z1 + z2 + z3;
    float sq = z0 * z0 + z1 * z1 + z2 * z2 + z3 * z3;
#pragma unroll
    for (int off = 16; off > 0; off >>= 1) {
        s  += __shfl_xor_sync(0xffffffffu, s, off);
        sq += __shfl_xor_sync(0xffffffffu, sq, off);
    }
    __shared__ float ws[8], wsq[8];
    __shared__ float mu_s, rstd_s;
    const int warp = t >> 5, lane = t & 31;
    if (lane == 0) { ws[warp] = s; wsq[warp] = sq; }
    __syncthreads();
    if (t == 0) {
        float ts = 0.f, tsq = 0.f;
#pragma unroll
        for (int wdx = 0; wdx < 8; wdx++) { ts += ws[wdx]; tsq += wsq[wdx]; }
        float mu = ts * (1.f / EMBED);
        float var = tsq * (1.f / EMBED) - mu * mu;
        mu_s = mu;
        rstd_s = rsqrtf(var + 1e-5f);
    }
    __syncthreads();
    float mu = mu_s, rstd = rstd_s;
    float4 gv = *(const float4*)(g + t * 4);
    float4 bv = *(const float4*)(be + t * 4);
    float4 out;
    out.x = (z0 - mu) * rstd * gv.x + bv.x;
    out.y = (z1 - mu) * rstd * gv.y + bv.y;
    out.z = (z2 - mu) * rstd * gv.z + bv.z;
    out.w = (z3 - mu) * rstd * gv.w + bv.w;
    *(float4*)(y + base) = out;
}

// ---------------- launch ----------------
extern "C" void kernel_launch(void* const* d_in, const int* in_sizes, int n_in,
                              void* d_out, int out_size)
{
    static bool inited = false;
    static float *pq, *pk, *pv, *pattn, *pproj, *px, *px2, *pff;
    if (!inited) {
        cudaGetSymbolAddress((void**)&pq,    g_q);
        cudaGetSymbolAddress((void**)&pk,    g_k);
        cudaGetSymbolAddress((void**)&pv,    g_v);
        cudaGetSymbolAddress((void**)&pattn, g_attn);
        cudaGetSymbolAddress((void**)&pproj, g_proj);
        cudaGetSymbolAddress((void**)&px,    g_x);
        cudaGetSymbolAddress((void**)&px2,   g_x2);
        cudaGetSymbolAddress((void**)&pff,   g_ffbuf);
        cudaFuncSetAttribute(band_attn, cudaFuncAttributeMaxDynamicSharedMemorySize,
                             ATTN_SMEM_BYTES);
        inited = true;
    }

    const float* x   = (const float*)d_in[0];
    const float* Wq  = (const float*)d_in[1];
    const float* bq  = (const float*)d_in[2];
    const float* Wk  = (const float*)d_in[3];
    const float* bk  = (const float*)d_in[4];
    const float* Wv  = (const float*)d_in[5];
    const float* bv  = (const float*)d_in[6];
    const float* Wo  = (const float*)d_in[7];
    const float* bo  = (const float*)d_in[8];
    const float* W1  = (const float*)d_in[9];
    const float* b1  = (const float*)d_in[10];
    const float* W2  = (const float*)d_in[11];
    const float* b2  = (const float*)d_in[12];
    const float* g1  = (const float*)d_in[13];
    const float* be1 = (const float*)d_in[14];
    const float* g2  = (const float*)d_in[15];
    const float* be2 = (const float*)d_in[16];
    float* out = (float*)d_out;

    const dim3 gE(EMBED / 128, ROWS / 128);   // (8, 32)
    const dim3 gF(FFDIM / 128, ROWS / 128);   // (32, 32)
    const dim3 gA(SEQ / QT, HEADS, BATCH);    // (32, 16, 2)

    const float* cur = x;
    for (int L = 0; L < LAYERS; L++) {
        const size_t oEE = (size_t)L * EMBED * EMBED;
        const size_t oE  = (size_t)L * EMBED;
        const size_t oFE = (size_t)L * FFDIM * EMBED;
        const size_t oF  = (size_t)L * FFDIM;

        sgemm_nt<<<gE, 256>>>(cur, Wq + oEE, bq + oE, pq, ROWS, EMBED, EMBED, 0);
        sgemm_nt<<<gE, 256>>>(cur, Wk + oEE, bk + oE, pk, ROWS, EMBED, EMBED, 0);
        sgemm_nt<<<gE, 256>>>(cur, Wv + oEE, bv + oE, pv, ROWS, EMBED, EMBED, 0);

        band_attn<<<gA, 256, ATTN_SMEM_BYTES>>>(pq, pk, pv, pattn);

        sgemm_nt<<<gE, 256>>>(pattn, Wo + oEE, bo + oE, pproj, ROWS, EMBED, EMBED, 0);
        add_ln<<<ROWS, 256>>>(cur, pproj, g1 + oE, be1 + oE, px2);

        sgemm_nt<<<gF, 256>>>(px2, W1 + oFE, b1 + oF, pff, ROWS, FFDIM, EMBED, 1);
        sgemm_nt<<<gE, 256>>>(pff, W2 + oFE, b2 + oE, pproj, ROWS, EMBED, FFDIM, 0);

        float* dst = (L == LAYERS - 1) ? out : px;
        add_ln<<<ROWS, 256>>>(px2, pproj, g2 + oE, be2 + oE, dst);
        cur = px;
    }
}